// round 13
// baseline (speedup 1.0000x reference)
#include <cuda_runtime.h>
#include <cuda_bf16.h>
#include <math.h>
#include <cstdint>

#define BATCH 8192
#define NVRT  778
#define NJO   21
#define NF    135
#define NM    336      /* 21*16 */
#define NN    1008     /* NM*3  */
#define NNP   1024
#define NFC   405      /* NF*3  */
#define PPLD  784
#define KSPLIT 8
#define KSEG  98       /* PPLD / KSPLIT */

#define BT    28       /* batches per epilogue tile */
#define NTILE 293      /* ceil(8192/28) */

#define PFK   160      /* padded K row stride (bf16); 136 used, tail stays 0 */

// ---------------- scratch (__device__ globals; zero-init; padding never written) ----
__device__ float g_vsh[NVRT * 3];
__device__ float g_Jk[64];
__device__ float g_W2T[NM * PPLD];
__device__ float g_Pp[NFC * PPLD];
__device__ float g_M[NM];
__device__ float g_C0[NNP];               // [1008..1024) stays 0
__device__ float g_Dp[KSPLIT * NF * NNP];
__device__ float g_D[NF * NNP];
__device__ __nv_bfloat16 g_pfh[BATCH * PFK];   // pf hi  (k=135 -> 1.0; tail 0)
__device__ __nv_bfloat16 g_pfl[BATCH * PFK];   // pf lo
__device__ __nv_bfloat16 g_DhT[NNP * PFK];     // D^T hi: [n][k] (k=135 -> C0; tail 0)
__device__ __nv_bfloat16 g_DlT[NNP * PFK];     // D^T lo
__device__ float g_P[BATCH * NNP];             // GEMM output P

// ================ stage A: vsh + W2T (25 blocks)  ||  Pp transpose ========
#define PP_BLKS ((NFC * NVRT + 255) / 256)
__global__ void k_A(const float* __restrict__ us, const float* __restrict__ sd,
                    const float* __restrict__ vt, const float* __restrict__ Jr,
                    const float* __restrict__ wg, const float* __restrict__ pd) {
    int t = threadIdx.x;
    if (blockIdx.x < 25) {
        __shared__ float jrs[32 * 21];
        __shared__ float wgs[32 * 17];
        int v0 = blockIdx.x * 32;
        int nv = NVRT - v0; if (nv > 32) nv = 32;
        for (int i = t; i < nv * 21; i += 256) jrs[i] = Jr[v0 * 21 + i];
        for (int i = t; i < nv * 16; i += 256) {
            int vl = i >> 4, j = i & 15;
            wgs[vl * 17 + j] = wg[(v0 + vl) * 16 + j];
        }
        for (int i = t; i < nv * 3; i += 256) {
            int g = v0 * 3 + i;
            float s = vt[g];
#pragma unroll
            for (int q = 0; q < 10; q++) s += us[q] * sd[q * 2334 + g];
            g_vsh[g] = s;
        }
        __syncthreads();
        for (int i = t; i < NM * 32; i += 256) {
            int vl = i & 31, m = i >> 5;
            int v = v0 + vl;
            if (v < NVRT)
                g_W2T[m * PPLD + v] = jrs[vl * 21 + (m >> 4)] * wgs[vl * 17 + (m & 15)];
        }
    } else {
        int idx = (blockIdx.x - 25) * 256 + t;
        if (idx < NFC * NVRT) {
            int fc = idx / NVRT, v = idx - fc * NVRT;
            int f = fc / 3, c = fc - 3 * f;
            g_Pp[fc * PPLD + v] = pd[f * 2334 + 3 * v + c];
        }
    }
}

// ================ pf rodrigues -> bf16 hi/lo split ================
__global__ void k_pf2(const float* __restrict__ theta) {
    int idx = blockIdx.x * 256 + threadIdx.x;   // BATCH*16 exact
    int b = idx >> 4, s = idx & 15;
    if (s == 15) {
        g_pfh[b * PFK + 135] = __float2bfloat16(1.0f);
        g_pfl[b * PFK + 135] = __float2bfloat16(0.0f);
        return;
    }
    const float* th = theta + b * 45 + 3 * s;
    float tx = th[0], ty = th[1], tz = th[2];
    float ax = tx + 1e-8f, ay = ty + 1e-8f, az = tz + 1e-8f;
    float angle = sqrtf(ax * ax + ay * ay + az * az);
    float inv = 1.0f / angle;
    float nx = tx * inv, ny = ty * inv, nz = tz * inv;
    float sh, ch;
    sincosf(0.5f * angle, &sh, &ch);
    float qw = ch, qx = sh * nx, qy = sh * ny, qz = sh * nz;
    float qn = rsqrtf(qw * qw + qx * qx + qy * qy + qz * qz);
    qw *= qn; qx *= qn; qy *= qn; qz *= qn;
    float w2 = qw * qw, x2 = qx * qx, y2 = qy * qy, z2 = qz * qz;
    float wx = qw * qx, wy = qw * qy, wz = qw * qz;
    float xy = qx * qy, xz = qx * qz, yz = qy * qz;
    float o[9];
    o[0] = w2 + x2 - y2 - z2 - 1.0f;
    o[1] = 2.f * (xy - wz);
    o[2] = 2.f * (wy + xz);
    o[3] = 2.f * (wz + xy);
    o[4] = w2 - x2 + y2 - z2 - 1.0f;
    o[5] = 2.f * (yz - wx);
    o[6] = 2.f * (xz - wy);
    o[7] = 2.f * (wx + yz);
    o[8] = w2 - x2 - y2 + z2 - 1.0f;
#pragma unroll
    for (int e = 0; e < 9; e++) {
        float x = o[e];
        __nv_bfloat16 h = __float2bfloat16(x);
        g_pfh[b * PFK + 9 * s + e] = h;
        g_pfl[b * PFK + 9 * s + e] = __float2bfloat16(x - __bfloat162float(h));
    }
}

// ================ stage B: Jk/M/C0  ||  D split-K partials ====
__global__ void k_B(const float* __restrict__ Jr) {
    int t = threadIdx.x;
    int blk = blockIdx.x;
    if (blk < NM + 63) {
        __shared__ float vs[NVRT * 3];
        __shared__ float red[4][256];
        for (int i = t; i < NVRT * 3; i += 256) vs[i] = g_vsh[i];
        __syncthreads();
        if (blk < NM) {
            int m = blk;
            float sm = 0.f, s0 = 0.f, s1 = 0.f, s2 = 0.f;
            for (int v = t; v < NVRT; v += 256) {
                float w = g_W2T[m * PPLD + v];
                sm += w;
                s0 += w * vs[v * 3 + 0];
                s1 += w * vs[v * 3 + 1];
                s2 += w * vs[v * 3 + 2];
            }
            red[0][t] = sm; red[1][t] = s0; red[2][t] = s1; red[3][t] = s2;
            __syncthreads();
            for (int o = 128; o > 0; o >>= 1) {
                if (t < o) {
                    red[0][t] += red[0][t + o]; red[1][t] += red[1][t + o];
                    red[2][t] += red[2][t + o]; red[3][t] += red[3][t + o];
                }
                __syncthreads();
            }
            if (t == 0) {
                g_M[m] = red[0][0];
                g_C0[m * 3 + 0] = red[1][0];
                g_C0[m * 3 + 1] = red[2][0];
                g_C0[m * 3 + 2] = red[3][0];
            }
        } else {
            int idx = blk - NM;
            int j = idx / 3, c = idx - 3 * j;
            float s = 0.f;
            for (int v = t; v < NVRT; v += 256) s += vs[v * 3 + c] * Jr[v * 21 + j];
            red[0][t] = s; __syncthreads();
            for (int o = 128; o > 0; o >>= 1) {
                if (t < o) red[0][t] += red[0][t + o];
                __syncthreads();
            }
            if (t == 0) g_Jk[j * 3 + c] = red[0][0];
        }
    } else {
        __shared__ float As[32][33];
        __shared__ float Bs[32][33];
        int b2 = blk - (NM + 63);
        int ks = b2 / 143;
        int rem = b2 - ks * 143;
        int m0 = (rem % 11) * 32;
        int fc0 = (rem / 11) * 32;
        int kbase = ks * KSEG, kend = kbase + KSEG;
        int tx = t & 15, ty = t >> 4;
        float acc[2][2] = {};
        for (int k0 = kbase; k0 < kend; k0 += 32) {
#pragma unroll
            for (int r = 0; r < 4; r++) {
                int e = t + 256 * r; int kk = e & 31, fl = e >> 5;
                int fc = fc0 + fl, k = k0 + kk;
                As[fl][kk] = (fc < NFC && k < kend) ? g_Pp[fc * PPLD + k] : 0.f;
            }
#pragma unroll
            for (int r = 0; r < 4; r++) {
                int e = t + 256 * r; int kk = e & 31, ml = e >> 5;
                int m = m0 + ml, k = k0 + kk;
                Bs[ml][kk] = (m < NM && k < kend) ? g_W2T[m * PPLD + k] : 0.f;
            }
            __syncthreads();
#pragma unroll
            for (int kk = 0; kk < 32; kk++) {
                float a0 = As[ty][kk], a1 = As[ty + 16][kk];
                float b0 = Bs[tx][kk], b1 = Bs[tx + 16][kk];
                acc[0][0] += a0 * b0; acc[0][1] += a0 * b1;
                acc[1][0] += a1 * b0; acc[1][1] += a1 * b1;
            }
            __syncthreads();
        }
#pragma unroll
        for (int i = 0; i < 2; i++) {
            int fc = fc0 + ty + 16 * i;
            if (fc >= NFC) continue;
            int f = fc / 3, c = fc - 3 * f;
#pragma unroll
            for (int jj = 0; jj < 2; jj++) {
                int m = m0 + tx + 16 * jj;
                if (m < NM) g_Dp[(ks * NF + f) * NNP + m * 3 + c] = acc[i][jj];
            }
        }
    }
}

// ================ combine split-K partials ================
__global__ void k_red() {
    int idx = blockIdx.x * 256 + threadIdx.x;
    const int S = NF * NNP;
    float s = 0.f;
#pragma unroll
    for (int k = 0; k < KSPLIT; k++) s += g_Dp[k * S + idx];
    g_D[idx] = s;
}

// ================ split D (+C0 as row 135) into transposed bf16 hi/lo ====
__global__ void k_Dsplit() {
    int idx = blockIdx.x * 256 + threadIdx.x;   // 136*1024 exact
    int k = idx >> 10, n = idx & 1023;
    float x = (k < NF) ? g_D[k * NNP + n] : g_C0[n];
    __nv_bfloat16 h = __float2bfloat16(x);
    g_DhT[n * PFK + k] = h;
    g_DlT[n * PFK + k] = __float2bfloat16(x - __bfloat162float(h));
}

// ================ mma.sync GEMM: P[8192][1024] = pf_ext @ D_ext ================
// Per CTA: M=128 batches, N=128 cols, K=144 (9 steps of 16), bf16 hi/lo split
// (3 HMMA terms: hh + hl + lh). 256 threads, warp grid 4m x 2n (warp = 32x64).
// 4 smem panels (Ah, Al, Bh, Bl): 128 rows x 144 k bf16, row stride 336 B
// (84 u32: 84 mod 32 = 20 -> ldmatrix rows hit distinct banks).
#define PROW   336                 /* bytes per smem panel row */
#define PANEL  (128 * PROW)        /* 43008 */
#define MM_SMEM (4 * PANEL)        /* 172032 */

__device__ __forceinline__ uint32_t s2u(const void* p) {
    uint32_t a;
    asm("{ .reg .u64 t; cvta.to.shared.u64 t, %1; cvt.u32.u64 %0, t; }" : "=r"(a) : "l"(p));
    return a;
}
__device__ __forceinline__ void ldm4(uint32_t* r, uint32_t addr) {
    asm volatile("ldmatrix.sync.aligned.m8n8.x4.shared.b16 {%0,%1,%2,%3}, [%4];"
                 : "=r"(r[0]), "=r"(r[1]), "=r"(r[2]), "=r"(r[3]) : "r"(addr));
}
__device__ __forceinline__ void mmabf(float* c, const uint32_t* a, uint32_t b0, uint32_t b1) {
    asm volatile(
        "mma.sync.aligned.m16n8k16.row.col.f32.bf16.bf16.f32 "
        "{%0,%1,%2,%3}, {%4,%5,%6,%7}, {%8,%9}, {%0,%1,%2,%3};"
        : "+f"(c[0]), "+f"(c[1]), "+f"(c[2]), "+f"(c[3])
        : "r"(a[0]), "r"(a[1]), "r"(a[2]), "r"(a[3]), "r"(b0), "r"(b1));
}

__global__ __launch_bounds__(256, 1)
void k_mma() {
    extern __shared__ char smc[];
    char* AH = smc;
    char* AL = smc + PANEL;
    char* BH = smc + 2 * PANEL;
    char* BL = smc + 3 * PANEL;

    int t = threadIdx.x, wid = t >> 5, lane = t & 31;
    int mt = blockIdx.x >> 3, nt = blockIdx.x & 7;
    int b0 = mt * 128, n0 = nt * 128;

    // ---- stage all 4 panels (rows: 18 uint4 = k 0..143) ----
    for (int i = t; i < 128 * 18; i += 256) {
        int r = i / 18, c = i - r * 18;
        uint32_t so = (uint32_t)(r * PROW + c * 16);
        uint64_t ga = (uint64_t)(b0 + r) * PFK + c * 8;
        uint64_t gb = (uint64_t)(n0 + r) * PFK + c * 8;
        *(uint4*)(AH + so) = *(const uint4*)&g_pfh[ga];
        *(uint4*)(AL + so) = *(const uint4*)&g_pfl[ga];
        *(uint4*)(BH + so) = *(const uint4*)&g_DhT[gb];
        *(uint4*)(BL + so) = *(const uint4*)&g_DlT[gb];
    }
    __syncthreads();

    int wm = wid >> 1, wn = wid & 1;
    int mbase = wm * 32, nbase = wn * 64;

    // per-lane ldmatrix offsets (bytes within panel)
    uint32_t aoff = (uint32_t)((mbase + (lane & 15)) * PROW + ((lane >> 4) & 1) * 16);
    uint32_t boff = (uint32_t)((nbase + (lane & 7) + ((lane >> 4) & 1) * 8) * PROW
                               + ((lane >> 3) & 1) * 16);
    uint32_t sAH = s2u(AH) + aoff, sAL = s2u(AL) + aoff;
    uint32_t sBH = s2u(BH) + boff, sBL = s2u(BL) + boff;

    float acc[2][8][4];
#pragma unroll
    for (int mi = 0; mi < 2; mi++)
#pragma unroll
        for (int ni = 0; ni < 8; ni++)
#pragma unroll
            for (int e = 0; e < 4; e++) acc[mi][ni][e] = 0.f;

#pragma unroll
    for (int ks = 0; ks < 9; ks++) {
        uint32_t ka = (uint32_t)(ks * 32);          // k0*2 bytes
        uint32_t Ah[2][4], Al[2][4];
        ldm4(Ah[0], sAH + ka);
        ldm4(Ah[1], sAH + 16 * PROW + ka);
        ldm4(Al[0], sAL + ka);
        ldm4(Al[1], sAL + 16 * PROW + ka);
#pragma unroll
        for (int np = 0; np < 4; np++) {
            uint32_t Bh[4], Bl[4];
            ldm4(Bh, sBH + np * 16 * PROW + ka);
            ldm4(Bl, sBL + np * 16 * PROW + ka);
#pragma unroll
            for (int mi = 0; mi < 2; mi++) {
#pragma unroll
                for (int hf = 0; hf < 2; hf++) {
                    float* c = acc[mi][2 * np + hf];
                    mmabf(c, Ah[mi], Bh[2 * hf], Bh[2 * hf + 1]);
                    mmabf(c, Ah[mi], Bl[2 * hf], Bl[2 * hf + 1]);
                    mmabf(c, Al[mi], Bh[2 * hf], Bh[2 * hf + 1]);
                }
            }
        }
    }

    // ---- store P fragments ----
    int gid = lane >> 2, tig = lane & 3;
#pragma unroll
    for (int mi = 0; mi < 2; mi++) {
        int row = b0 + mbase + mi * 16 + gid;
#pragma unroll
        for (int ni = 0; ni < 8; ni++) {
            int col = n0 + nbase + ni * 8 + tig * 2;
            const float* c = acc[mi][ni];
            *(float2*)&g_P[(uint64_t)row * NNP + col] = make_float2(c[0], c[1]);
            *(float2*)&g_P[(uint64_t)(row + 8) * NNP + col] = make_float2(c[2], c[3]);
        }
    }
}

// ================ epilogue: pose + chain + joints (reads g_P) ================
#define SMEM_EPI (34080 * 4)
__global__ __launch_bounds__(256, 1)
void k_epi(const float* __restrict__ theta, const float* __restrict__ dq,
           const float* __restrict__ iq, const float* __restrict__ tr,
           float* __restrict__ out) {
    extern __shared__ float sm[];
    float* Ps  = sm;
    float* Asm = sm + 28224;
    float* Ms  = sm + 33600;
    float* Ts  = sm + 33936;
    float* Jks = sm + 34032;
    float* ths = sm;
    float* pff = sm + 1264;

    int t = threadIdx.x;
    int b0 = blockIdx.x * BT;
    int nb = BATCH - b0; if (nb > BT) nb = BT;

    for (int i = t; i < nb * 45; i += 256) ths[i] = theta[b0 * 45 + i];
    if (t >= 96 && t < 144) { int i = t - 96; Jks[i] = g_Jk[i]; }
    for (int i = t; i < NM; i += 256) Ms[i] = g_M[i];
    if (t < nb * 3) Ts[t] = tr[b0 * 3 + t];
    __syncthreads();

    for (int it = t; it < nb * 15; it += 256) {
        int bl = it / 15, i = it - bl * 15;
        const float* th = ths + bl * 45 + 3 * i;
        float tx = th[0], ty = th[1], tz = th[2];
        float ax = tx + 1e-8f, ay = ty + 1e-8f, az = tz + 1e-8f;
        float angle = sqrtf(ax * ax + ay * ay + az * az);
        float inv = 1.0f / angle;
        float nx = tx * inv, ny = ty * inv, nz = tz * inv;
        float sh, ch;
        sincosf(0.5f * angle, &sh, &ch);
        float qw = ch, qx = sh * nx, qy = sh * ny, qz = sh * nz;
        float qn = rsqrtf(qw * qw + qx * qx + qy * qy + qz * qz);
        qw *= qn; qx *= qn; qy *= qn; qz *= qn;
        float w2 = qw * qw, x2 = qx * qx, y2 = qy * qy, z2 = qz * qz;
        float wx = qw * qx, wy = qw * qy, wz = qw * qz;
        float xy = qx * qy, xz = qx * qz, yz = qy * qz;
        float o[9];
        o[0] = w2 + x2 - y2 - z2 - 1.0f;
        o[1] = 2.f * (xy - wz);
        o[2] = 2.f * (wy + xz);
        o[3] = 2.f * (wz + xy);
        o[4] = w2 - x2 + y2 - z2 - 1.0f;
        o[5] = 2.f * (yz - wx);
        o[6] = 2.f * (xz - wy);
        o[7] = 2.f * (wx + yz);
        o[8] = w2 - x2 - y2 + z2 - 1.0f;
        int pr = bl >> 1, lo = bl & 1;
#pragma unroll
        for (int e = 0; e < 9; e++)
            pff[(9 * i + e) * 32 + pr * 2 + lo] = o[e];
    }
    __syncthreads();

    if (t < nb * 3) {
        int bl = t / 3, k = t - bl * 3;
        int b = b0 + bl;
        float w1 = dq[b * 4 + 0], x1 = dq[b * 4 + 1], y1 = dq[b * 4 + 2], z1 = dq[b * 4 + 3];
        float w2q = iq[0], x2q = iq[1], y2q = iq[2], z2q = iq[3];
        float qw = w1 * w2q - x1 * x2q - y1 * y2q - z1 * z2q;
        float qx = w1 * x2q + x1 * w2q + y1 * z2q - z1 * y2q;
        float qy = w1 * y2q - x1 * z2q + y1 * w2q + z1 * x2q;
        float qz = w1 * z2q + x1 * y2q - y1 * x2q + z1 * w2q;
        float qn = rsqrtf(qw * qw + qx * qx + qy * qy + qz * qz);
        qw *= qn; qx *= qn; qy *= qn; qz *= qn;
        float W2_ = qw * qw, X2 = qx * qx, Y2 = qy * qy, Z2 = qz * qz;
        float WX = qw * qx, WY = qw * qy, WZ = qw * qz;
        float XY = qx * qy, XZ = qx * qz, YZ = qy * qz;
        float R[9];
        R[0] = W2_ + X2 - Y2 - Z2; R[1] = 2.f * (XY - WZ);    R[2] = 2.f * (WY + XZ);
        R[3] = 2.f * (WZ + XY);    R[4] = W2_ - X2 + Y2 - Z2; R[5] = 2.f * (YZ - WX);
        R[6] = 2.f * (XZ - WY);    R[7] = 2.f * (WX + YZ);    R[8] = W2_ - X2 - Y2 + Z2;

        float rr0 = R[3 * k + 0], rr1 = R[3 * k + 1], rr2 = R[3 * k + 2];
        float rt = Jks[k];
        float* Ao = Asm + bl * 192;
        {
            float jx = Jks[0], jy = Jks[1], jz = Jks[2];
            Ao[k * 3 + 0] = rr0; Ao[k * 3 + 1] = rr1; Ao[k * 3 + 2] = rr2;
            Ao[9 + k] = rt - (rr0 * jx + rr1 * jy + rr2 * jz);
        }
        int pr = bl >> 1, lo = bl & 1;
#pragma unroll
        for (int chn = 0; chn < 5; chn++) {
            float cr0 = rr0, cr1 = rr1, cr2 = rr2, ct = rt;
#pragma unroll
            for (int s = 0; s < 3; s++) {
                int i = chn * 3 + 1 + s;
                int p = (s == 0) ? 0 : (i - 1);
                float Ri[9];
#pragma unroll
                for (int e = 0; e < 9; e++)
                    Ri[e] = pff[(9 * (i - 1) + e) * 32 + pr * 2 + lo]
                          + ((e == 0 || e == 4 || e == 8) ? 1.0f : 0.0f);
                float rx = Jks[3 * i + 0] - Jks[3 * p + 0];
                float ry = Jks[3 * i + 1] - Jks[3 * p + 1];
                float rz = Jks[3 * i + 2] - Jks[3 * p + 2];
                float n0 = cr0 * Ri[0] + cr1 * Ri[3] + cr2 * Ri[6];
                float n1 = cr0 * Ri[1] + cr1 * Ri[4] + cr2 * Ri[7];
                float n2 = cr0 * Ri[2] + cr1 * Ri[5] + cr2 * Ri[8];
                float nt = cr0 * rx + cr1 * ry + cr2 * rz + ct;
                float jx = Jks[3 * i + 0], jy = Jks[3 * i + 1], jz = Jks[3 * i + 2];
                float* Aoi = Ao + i * 12;
                Aoi[k * 3 + 0] = n0; Aoi[k * 3 + 1] = n1; Aoi[k * 3 + 2] = n2;
                Aoi[9 + k] = nt - (n0 * jx + n1 * jy + n2 * jz);
                cr0 = n0; cr1 = n1; cr2 = n2; ct = nt;
            }
        }
    }
    __syncthreads();   // chain done; pff/ths dead

    for (int i = t; i < nb * 252; i += 256) {
        int row = i / 252, c4 = i - row * 252;
        *(float4*)&Ps[row * NN + 4 * c4] =
            *(const float4*)&g_P[(uint64_t)(b0 + row) * NNP + 4 * c4];
    }
    __syncthreads();

    for (int idx = t; idx < nb * 63; idx += 256) {
        int bl = idx / 63;
        int r = idx - bl * 63;
        int jo = r / 3;
        int k = r - jo * 3;
        const float* Ab = Asm + bl * 192;
        const float* Pb = Ps + bl * NN;
        float s = Ts[bl * 3 + k];
#pragma unroll
        for (int j = 0; j < 16; j++) {
            int rb = j * 12 + k * 3;
            int pb = (jo * 16 + j) * 3;
            s += Ab[rb] * Pb[pb] + Ab[rb + 1] * Pb[pb + 1] + Ab[rb + 2] * Pb[pb + 2]
               + Ms[jo * 16 + j] * Ab[j * 12 + 9 + k];
        }
        out[(b0 + bl) * 63 + jo * 3 + k] = s;
    }
}

// ---------------- launcher ----------------
extern "C" void kernel_launch(void* const* d_in, const int* in_sizes, int n_in,
                              void* d_out, int out_size) {
    const float* theta = (const float*)d_in[0];
    const float* dq    = (const float*)d_in[1];
    const float* us    = (const float*)d_in[2];
    const float* iq    = (const float*)d_in[3];
    const float* tr    = (const float*)d_in[4];
    const float* vt    = (const float*)d_in[5];
    const float* sd    = (const float*)d_in[6];
    const float* Jr    = (const float*)d_in[7];
    const float* pd    = (const float*)d_in[8];
    const float* wg    = (const float*)d_in[9];
    float* out = (float*)d_out;

    cudaFuncSetAttribute(k_mma, cudaFuncAttributeMaxDynamicSharedMemorySize, MM_SMEM);
    cudaFuncSetAttribute(k_epi, cudaFuncAttributeMaxDynamicSharedMemorySize, SMEM_EPI);

    k_A<<<25 + PP_BLKS, 256>>>(us, sd, vt, Jr, wg, pd);
    k_pf2<<<(BATCH * 16) / 256, 256>>>(theta);
    k_B<<<NM + 63 + 143 * KSPLIT, 256>>>(Jr);
    k_red<<<(NF * NNP) / 256, 256>>>();
    k_Dsplit<<<(136 * 1024) / 256, 256>>>();
    k_mma<<<512, 256, MM_SMEM>>>();
    k_epi<<<NTILE, 256, SMEM_EPI>>>(theta, dq, iq, tr, out);
}

// round 14
// speedup vs baseline: 1.0588x; 1.0588x over previous
#include <cuda_runtime.h>
#include <cuda_bf16.h>
#include <math.h>
#include <cstdint>

#define BATCH 8192
#define NVRT  778
#define NJO   21
#define NF    135
#define NM    336      /* 21*16 */
#define NN    1008     /* NM*3  */
#define NNP   1024
#define NFC   405      /* NF*3  */
#define PPLD  784
#define KSPLIT 8
#define KSEG  98       /* PPLD / KSPLIT */

#define BT    28       /* batches per epilogue tile */
#define NTILE 293      /* ceil(8192/28) */

#define PFK   160      /* padded K row stride (bf16); 144 touched, tail stays 0 */

// ---------------- scratch (__device__ globals; zero-init; padding never written) ----
__device__ float g_vsh[NVRT * 3];
__device__ float g_Jk[64];
__device__ float g_W2T[NM * PPLD];
__device__ float g_Pp[NFC * PPLD];
__device__ float g_M[NM];
__device__ float g_C0[NNP];               // [1008..1024) stays 0
__device__ float g_Dp[KSPLIT * NF * NNP];
__device__ __nv_bfloat16 g_pfh[BATCH * PFK];   // pf hi  (k=135 -> 1.0; tail 0)
__device__ __nv_bfloat16 g_pfl[BATCH * PFK];   // pf lo
__device__ __nv_bfloat16 g_DhT[NNP * PFK];     // D^T hi: [n][k] (k=135 -> C0; tail 0)
__device__ __nv_bfloat16 g_DlT[NNP * PFK];     // D^T lo
__device__ float g_P[BATCH * NNP];             // GEMM output P

// ================ stage A: vsh+W2T (25)  ||  Pp transpose (1231)  ||  pf split (512) ====
#define PP_BLKS ((NFC * NVRT + 255) / 256)
__global__ void k_A(const float* __restrict__ us, const float* __restrict__ sd,
                    const float* __restrict__ vt, const float* __restrict__ Jr,
                    const float* __restrict__ wg, const float* __restrict__ pd,
                    const float* __restrict__ theta) {
    int t = threadIdx.x;
    if (blockIdx.x < 25) {
        __shared__ float jrs[32 * 21];
        __shared__ float wgs[32 * 17];
        int v0 = blockIdx.x * 32;
        int nv = NVRT - v0; if (nv > 32) nv = 32;
        for (int i = t; i < nv * 21; i += 256) jrs[i] = Jr[v0 * 21 + i];
        for (int i = t; i < nv * 16; i += 256) {
            int vl = i >> 4, j = i & 15;
            wgs[vl * 17 + j] = wg[(v0 + vl) * 16 + j];
        }
        for (int i = t; i < nv * 3; i += 256) {
            int g = v0 * 3 + i;
            float s = vt[g];
#pragma unroll
            for (int q = 0; q < 10; q++) s += us[q] * sd[q * 2334 + g];
            g_vsh[g] = s;
        }
        __syncthreads();
        for (int i = t; i < NM * 32; i += 256) {
            int vl = i & 31, m = i >> 5;
            int v = v0 + vl;
            if (v < NVRT)
                g_W2T[m * PPLD + v] = jrs[vl * 21 + (m >> 4)] * wgs[vl * 17 + (m & 15)];
        }
    } else if (blockIdx.x < 25 + PP_BLKS) {
        int idx = (blockIdx.x - 25) * 256 + t;
        if (idx < NFC * NVRT) {
            int fc = idx / NVRT, v = idx - fc * NVRT;
            int f = fc / 3, c = fc - 3 * f;
            g_Pp[fc * PPLD + v] = pd[f * 2334 + 3 * v + c];
        }
    } else {
        int idx = (blockIdx.x - 25 - PP_BLKS) * 256 + t;  // BATCH*16 exact
        int b = idx >> 4, s = idx & 15;
        if (s == 15) {
            g_pfh[b * PFK + 135] = __float2bfloat16(1.0f);
            return;
        }
        const float* th = theta + b * 45 + 3 * s;
        float tx = th[0], ty = th[1], tz = th[2];
        float ax = tx + 1e-8f, ay = ty + 1e-8f, az = tz + 1e-8f;
        float angle = sqrtf(ax * ax + ay * ay + az * az);
        float inv = 1.0f / angle;
        float nx = tx * inv, ny = ty * inv, nz = tz * inv;
        float sh, ch;
        sincosf(0.5f * angle, &sh, &ch);
        float qw = ch, qx = sh * nx, qy = sh * ny, qz = sh * nz;
        float qn = rsqrtf(qw * qw + qx * qx + qy * qy + qz * qz);
        qw *= qn; qx *= qn; qy *= qn; qz *= qn;
        float w2 = qw * qw, x2 = qx * qx, y2 = qy * qy, z2 = qz * qz;
        float wx = qw * qx, wy = qw * qy, wz = qw * qz;
        float xy = qx * qy, xz = qx * qz, yz = qy * qz;
        float o[9];
        o[0] = w2 + x2 - y2 - z2 - 1.0f;
        o[1] = 2.f * (xy - wz);
        o[2] = 2.f * (wy + xz);
        o[3] = 2.f * (wz + xy);
        o[4] = w2 - x2 + y2 - z2 - 1.0f;
        o[5] = 2.f * (yz - wx);
        o[6] = 2.f * (xz - wy);
        o[7] = 2.f * (wx + yz);
        o[8] = w2 - x2 - y2 + z2 - 1.0f;
#pragma unroll
        for (int e = 0; e < 9; e++) {
            float x = o[e];
            __nv_bfloat16 h = __float2bfloat16(x);
            g_pfh[b * PFK + 9 * s + e] = h;
            g_pfl[b * PFK + 9 * s + e] = __float2bfloat16(x - __bfloat162float(h));
        }
    }
}

// ================ stage B: Jk/M/C0  ||  D split-K partials ====
__global__ void k_B(const float* __restrict__ Jr) {
    int t = threadIdx.x;
    int blk = blockIdx.x;
    if (blk < NM + 63) {
        __shared__ float vs[NVRT * 3];
        __shared__ float red[4][256];
        for (int i = t; i < NVRT * 3; i += 256) vs[i] = g_vsh[i];
        __syncthreads();
        if (blk < NM) {
            int m = blk;
            float sm = 0.f, s0 = 0.f, s1 = 0.f, s2 = 0.f;
            for (int v = t; v < NVRT; v += 256) {
                float w = g_W2T[m * PPLD + v];
                sm += w;
                s0 += w * vs[v * 3 + 0];
                s1 += w * vs[v * 3 + 1];
                s2 += w * vs[v * 3 + 2];
            }
            red[0][t] = sm; red[1][t] = s0; red[2][t] = s1; red[3][t] = s2;
            __syncthreads();
            for (int o = 128; o > 0; o >>= 1) {
                if (t < o) {
                    red[0][t] += red[0][t + o]; red[1][t] += red[1][t + o];
                    red[2][t] += red[2][t + o]; red[3][t] += red[3][t + o];
                }
                __syncthreads();
            }
            if (t == 0) {
                g_M[m] = red[0][0];
                g_C0[m * 3 + 0] = red[1][0];
                g_C0[m * 3 + 1] = red[2][0];
                g_C0[m * 3 + 2] = red[3][0];
            }
        } else {
            int idx = blk - NM;
            int j = idx / 3, c = idx - 3 * j;
            float s = 0.f;
            for (int v = t; v < NVRT; v += 256) s += vs[v * 3 + c] * Jr[v * 21 + j];
            red[0][t] = s; __syncthreads();
            for (int o = 128; o > 0; o >>= 1) {
                if (t < o) red[0][t] += red[0][t + o];
                __syncthreads();
            }
            if (t == 0) g_Jk[j * 3 + c] = red[0][0];
        }
    } else {
        __shared__ float As[32][33];
        __shared__ float Bs[32][33];
        int b2 = blk - (NM + 63);
        int ks = b2 / 143;
        int rem = b2 - ks * 143;
        int m0 = (rem % 11) * 32;
        int fc0 = (rem / 11) * 32;
        int kbase = ks * KSEG, kend = kbase + KSEG;
        int tx = t & 15, ty = t >> 4;
        float acc[2][2] = {};
        for (int k0 = kbase; k0 < kend; k0 += 32) {
#pragma unroll
            for (int r = 0; r < 4; r++) {
                int e = t + 256 * r; int kk = e & 31, fl = e >> 5;
                int fc = fc0 + fl, k = k0 + kk;
                As[fl][kk] = (fc < NFC && k < kend) ? g_Pp[fc * PPLD + k] : 0.f;
            }
#pragma unroll
            for (int r = 0; r < 4; r++) {
                int e = t + 256 * r; int kk = e & 31, ml = e >> 5;
                int m = m0 + ml, k = k0 + kk;
                Bs[ml][kk] = (m < NM && k < kend) ? g_W2T[m * PPLD + k] : 0.f;
            }
            __syncthreads();
#pragma unroll
            for (int kk = 0; kk < 32; kk++) {
                float a0 = As[ty][kk], a1 = As[ty + 16][kk];
                float b0 = Bs[tx][kk], b1 = Bs[tx + 16][kk];
                acc[0][0] += a0 * b0; acc[0][1] += a0 * b1;
                acc[1][0] += a1 * b0; acc[1][1] += a1 * b1;
            }
            __syncthreads();
        }
#pragma unroll
        for (int i = 0; i < 2; i++) {
            int fc = fc0 + ty + 16 * i;
            if (fc >= NFC) continue;
            int f = fc / 3, c = fc - 3 * f;
#pragma unroll
            for (int jj = 0; jj < 2; jj++) {
                int m = m0 + tx + 16 * jj;
                if (m < NM) g_Dp[(ks * NF + f) * NNP + m * 3 + c] = acc[i][jj];
            }
        }
    }
}

// ================ combine partials + bf16 hi/lo split + transpose (fused) ========
__global__ void k_red2() {
    int idx = blockIdx.x * 256 + threadIdx.x;   // 136*1024 exact
    int k = idx >> 10, n = idx & 1023;
    float x;
    if (k < NF) {
        const int S = NF * NNP;
        x = 0.f;
#pragma unroll
        for (int q = 0; q < KSPLIT; q++) x += g_Dp[q * S + k * NNP + n];
    } else {
        x = g_C0[n];
    }
    __nv_bfloat16 h = __float2bfloat16(x);
    g_DhT[n * PFK + k] = h;
    g_DlT[n * PFK + k] = __float2bfloat16(x - __bfloat162float(h));
}

// ================ mma.sync GEMM: P = pf_ext @ D_ext (2-phase K staging) ================
// Per CTA: M=128, N=128, K=144; bf16 hi/lo split (hh + hl + lh). 256 thr, warps 4m x 2n.
// Panels 128 rows x 176 B (per phase: k 0..79 then 80..143). smem 88 KB -> 2 CTAs/SM.
#define PROW   176
#define PANEL  (128 * PROW)        /* 22528 */
#define MM_SMEM (4 * PANEL)        /* 90112 */

__device__ __forceinline__ uint32_t s2u(const void* p) {
    uint32_t a;
    asm("{ .reg .u64 t; cvta.to.shared.u64 t, %1; cvt.u32.u64 %0, t; }" : "=r"(a) : "l"(p));
    return a;
}
__device__ __forceinline__ void ldm4(uint32_t* r, uint32_t addr) {
    asm volatile("ldmatrix.sync.aligned.m8n8.x4.shared.b16 {%0,%1,%2,%3}, [%4];"
                 : "=r"(r[0]), "=r"(r[1]), "=r"(r[2]), "=r"(r[3]) : "r"(addr));
}
__device__ __forceinline__ void mmabf(float* c, const uint32_t* a, uint32_t b0, uint32_t b1) {
    asm volatile(
        "mma.sync.aligned.m16n8k16.row.col.f32.bf16.bf16.f32 "
        "{%0,%1,%2,%3}, {%4,%5,%6,%7}, {%8,%9}, {%0,%1,%2,%3};"
        : "+f"(c[0]), "+f"(c[1]), "+f"(c[2]), "+f"(c[3])
        : "r"(a[0]), "r"(a[1]), "r"(a[2]), "r"(a[3]), "r"(b0), "r"(b1));
}

__global__ __launch_bounds__(256, 2)
void k_mma() {
    extern __shared__ char smc[];
    char* AH = smc;
    char* AL = smc + PANEL;
    char* BH = smc + 2 * PANEL;
    char* BL = smc + 3 * PANEL;

    int t = threadIdx.x, wid = t >> 5, lane = t & 31;
    int mt = blockIdx.x >> 3, nt = blockIdx.x & 7;
    int b0 = mt * 128, n0 = nt * 128;

    int wm = wid >> 1, wn = wid & 1;
    int mbase = wm * 32, nbase = wn * 64;
    uint32_t aoff = (uint32_t)((mbase + (lane & 15)) * PROW + ((lane >> 4) & 1) * 16);
    uint32_t boff = (uint32_t)((nbase + (lane & 7) + ((lane >> 4) & 1) * 8) * PROW
                               + ((lane >> 3) & 1) * 16);
    uint32_t sAH = s2u(AH) + aoff, sAL = s2u(AL) + aoff;
    uint32_t sBH = s2u(BH) + boff, sBL = s2u(BL) + boff;

    float acc[2][8][4];
#pragma unroll
    for (int mi = 0; mi < 2; mi++)
#pragma unroll
        for (int ni = 0; ni < 8; ni++)
#pragma unroll
            for (int e = 0; e < 4; e++) acc[mi][ni][e] = 0.f;

#pragma unroll
    for (int ph = 0; ph < 2; ph++) {
        int kb = ph ? 80 : 0;          // global k base (elements)
        int nc = ph ? 8 : 10;          // uint4 chunks per row
        int nks = ph ? 4 : 5;          // 16-k steps this phase
        // ---- stage panels for this phase ----
        for (int i = t; i < 128 * nc; i += 256) {
            int r = i / nc, c = i - r * nc;
            uint32_t so = (uint32_t)(r * PROW + c * 16);
            uint64_t ga = (uint64_t)(b0 + r) * PFK + kb + c * 8;
            uint64_t gb = (uint64_t)(n0 + r) * PFK + kb + c * 8;
            *(uint4*)(AH + so) = *(const uint4*)&g_pfh[ga];
            *(uint4*)(AL + so) = *(const uint4*)&g_pfl[ga];
            *(uint4*)(BH + so) = *(const uint4*)&g_DhT[gb];
            *(uint4*)(BL + so) = *(const uint4*)&g_DlT[gb];
        }
        __syncthreads();
        // ---- compute ----
        for (int ks = 0; ks < nks; ks++) {
            uint32_t ka = (uint32_t)(ks * 32);
            uint32_t Ah[2][4], Al[2][4];
            ldm4(Ah[0], sAH + ka);
            ldm4(Ah[1], sAH + 16 * PROW + ka);
            ldm4(Al[0], sAL + ka);
            ldm4(Al[1], sAL + 16 * PROW + ka);
#pragma unroll
            for (int np = 0; np < 4; np++) {
                uint32_t Bh[4], Bl[4];
                ldm4(Bh, sBH + np * 16 * PROW + ka);
                ldm4(Bl, sBL + np * 16 * PROW + ka);
#pragma unroll
                for (int mi = 0; mi < 2; mi++) {
#pragma unroll
                    for (int hf = 0; hf < 2; hf++) {
                        float* c = acc[mi][2 * np + hf];
                        mmabf(c, Ah[mi], Bh[2 * hf], Bh[2 * hf + 1]);
                        mmabf(c, Ah[mi], Bl[2 * hf], Bl[2 * hf + 1]);
                        mmabf(c, Al[mi], Bh[2 * hf], Bh[2 * hf + 1]);
                    }
                }
            }
        }
        __syncthreads();
    }

    // ---- store P fragments ----
    int gid = lane >> 2, tig = lane & 3;
#pragma unroll
    for (int mi = 0; mi < 2; mi++) {
        int row = b0 + mbase + mi * 16 + gid;
#pragma unroll
        for (int ni = 0; ni < 8; ni++) {
            int col = n0 + nbase + ni * 8 + tig * 2;
            const float* c = acc[mi][ni];
            *(float2*)&g_P[(uint64_t)row * NNP + col] = make_float2(c[0], c[1]);
            *(float2*)&g_P[(uint64_t)(row + 8) * NNP + col] = make_float2(c[2], c[3]);
        }
    }
}

// ================ epilogue: pose + chain + joints (reads g_P) ================
#define SMEM_EPI (34080 * 4)
__global__ __launch_bounds__(256, 1)
void k_epi(const float* __restrict__ theta, const float* __restrict__ dq,
           const float* __restrict__ iq, const float* __restrict__ tr,
           float* __restrict__ out) {
    extern __shared__ float sm[];
    float* Ps  = sm;
    float* Asm = sm + 28224;
    float* Ms  = sm + 33600;
    float* Ts  = sm + 33936;
    float* Jks = sm + 34032;
    float* ths = sm;
    float* pff = sm + 1264;

    int t = threadIdx.x;
    int b0 = blockIdx.x * BT;
    int nb = BATCH - b0; if (nb > BT) nb = BT;

    for (int i = t; i < nb * 45; i += 256) ths[i] = theta[b0 * 45 + i];
    if (t >= 96 && t < 144) { int i = t - 96; Jks[i] = g_Jk[i]; }
    for (int i = t; i < NM; i += 256) Ms[i] = g_M[i];
    if (t < nb * 3) Ts[t] = tr[b0 * 3 + t];
    __syncthreads();

    for (int it = t; it < nb * 15; it += 256) {
        int bl = it / 15, i = it - bl * 15;
        const float* th = ths + bl * 45 + 3 * i;
        float tx = th[0], ty = th[1], tz = th[2];
        float ax = tx + 1e-8f, ay = ty + 1e-8f, az = tz + 1e-8f;
        float angle = sqrtf(ax * ax + ay * ay + az * az);
        float inv = 1.0f / angle;
        float nx = tx * inv, ny = ty * inv, nz = tz * inv;
        float sh, ch;
        sincosf(0.5f * angle, &sh, &ch);
        float qw = ch, qx = sh * nx, qy = sh * ny, qz = sh * nz;
        float qn = rsqrtf(qw * qw + qx * qx + qy * qy + qz * qz);
        qw *= qn; qx *= qn; qy *= qn; qz *= qn;
        float w2 = qw * qw, x2 = qx * qx, y2 = qy * qy, z2 = qz * qz;
        float wx = qw * qx, wy = qw * qy, wz = qw * qz;
        float xy = qx * qy, xz = qx * qz, yz = qy * qz;
        float o[9];
        o[0] = w2 + x2 - y2 - z2 - 1.0f;
        o[1] = 2.f * (xy - wz);
        o[2] = 2.f * (wy + xz);
        o[3] = 2.f * (wz + xy);
        o[4] = w2 - x2 + y2 - z2 - 1.0f;
        o[5] = 2.f * (yz - wx);
        o[6] = 2.f * (xz - wy);
        o[7] = 2.f * (wx + yz);
        o[8] = w2 - x2 - y2 + z2 - 1.0f;
        int pr = bl >> 1, lo = bl & 1;
#pragma unroll
        for (int e = 0; e < 9; e++)
            pff[(9 * i + e) * 32 + pr * 2 + lo] = o[e];
    }
    __syncthreads();

    if (t < nb * 3) {
        int bl = t / 3, k = t - bl * 3;
        int b = b0 + bl;
        float w1 = dq[b * 4 + 0], x1 = dq[b * 4 + 1], y1 = dq[b * 4 + 2], z1 = dq[b * 4 + 3];
        float w2q = iq[0], x2q = iq[1], y2q = iq[2], z2q = iq[3];
        float qw = w1 * w2q - x1 * x2q - y1 * y2q - z1 * z2q;
        float qx = w1 * x2q + x1 * w2q + y1 * z2q - z1 * y2q;
        float qy = w1 * y2q - x1 * z2q + y1 * w2q + z1 * x2q;
        float qz = w1 * z2q + x1 * y2q - y1 * x2q + z1 * w2q;
        float qn = rsqrtf(qw * qw + qx * qx + qy * qy + qz * qz);
        qw *= qn; qx *= qn; qy *= qn; qz *= qn;
        float W2_ = qw * qw, X2 = qx * qx, Y2 = qy * qy, Z2 = qz * qz;
        float WX = qw * qx, WY = qw * qy, WZ = qw * qz;
        float XY = qx * qy, XZ = qx * qz, YZ = qy * qz;
        float R[9];
        R[0] = W2_ + X2 - Y2 - Z2; R[1] = 2.f * (XY - WZ);    R[2] = 2.f * (WY + XZ);
        R[3] = 2.f * (WZ + XY);    R[4] = W2_ - X2 + Y2 - Z2; R[5] = 2.f * (YZ - WX);
        R[6] = 2.f * (XZ - WY);    R[7] = 2.f * (WX + YZ);    R[8] = W2_ - X2 - Y2 + Z2;

        float rr0 = R[3 * k + 0], rr1 = R[3 * k + 1], rr2 = R[3 * k + 2];
        float rt = Jks[k];
        float* Ao = Asm + bl * 192;
        {
            float jx = Jks[0], jy = Jks[1], jz = Jks[2];
            Ao[k * 3 + 0] = rr0; Ao[k * 3 + 1] = rr1; Ao[k * 3 + 2] = rr2;
            Ao[9 + k] = rt - (rr0 * jx + rr1 * jy + rr2 * jz);
        }
        int pr = bl >> 1, lo = bl & 1;
#pragma unroll
        for (int chn = 0; chn < 5; chn++) {
            float cr0 = rr0, cr1 = rr1, cr2 = rr2, ct = rt;
#pragma unroll
            for (int s = 0; s < 3; s++) {
                int i = chn * 3 + 1 + s;
                int p = (s == 0) ? 0 : (i - 1);
                float Ri[9];
#pragma unroll
                for (int e = 0; e < 9; e++)
                    Ri[e] = pff[(9 * (i - 1) + e) * 32 + pr * 2 + lo]
                          + ((e == 0 || e == 4 || e == 8) ? 1.0f : 0.0f);
                float rx = Jks[3 * i + 0] - Jks[3 * p + 0];
                float ry = Jks[3 * i + 1] - Jks[3 * p + 1];
                float rz = Jks[3 * i + 2] - Jks[3 * p + 2];
                float n0 = cr0 * Ri[0] + cr1 * Ri[3] + cr2 * Ri[6];
                float n1 = cr0 * Ri[1] + cr1 * Ri[4] + cr2 * Ri[7];
                float n2 = cr0 * Ri[2] + cr1 * Ri[5] + cr2 * Ri[8];
                float nt = cr0 * rx + cr1 * ry + cr2 * rz + ct;
                float jx = Jks[3 * i + 0], jy = Jks[3 * i + 1], jz = Jks[3 * i + 2];
                float* Aoi = Ao + i * 12;
                Aoi[k * 3 + 0] = n0; Aoi[k * 3 + 1] = n1; Aoi[k * 3 + 2] = n2;
                Aoi[9 + k] = nt - (n0 * jx + n1 * jy + n2 * jz);
                cr0 = n0; cr1 = n1; cr2 = n2; ct = nt;
            }
        }
    }
    __syncthreads();   // chain done; pff/ths dead

    for (int i = t; i < nb * 252; i += 256) {
        int row = i / 252, c4 = i - row * 252;
        *(float4*)&Ps[row * NN + 4 * c4] =
            *(const float4*)&g_P[(uint64_t)(b0 + row) * NNP + 4 * c4];
    }
    __syncthreads();

    for (int idx = t; idx < nb * 63; idx += 256) {
        int bl = idx / 63;
        int r = idx - bl * 63;
        int jo = r / 3;
        int k = r - jo * 3;
        const float* Ab = Asm + bl * 192;
        const float* Pb = Ps + bl * NN;
        float s = Ts[bl * 3 + k];
#pragma unroll
        for (int j = 0; j < 16; j++) {
            int rb = j * 12 + k * 3;
            int pb = (jo * 16 + j) * 3;
            s += Ab[rb] * Pb[pb] + Ab[rb + 1] * Pb[pb + 1] + Ab[rb + 2] * Pb[pb + 2]
               + Ms[jo * 16 + j] * Ab[j * 12 + 9 + k];
        }
        out[(b0 + bl) * 63 + jo * 3 + k] = s;
    }
}

// ---------------- launcher ----------------
extern "C" void kernel_launch(void* const* d_in, const int* in_sizes, int n_in,
                              void* d_out, int out_size) {
    const float* theta = (const float*)d_in[0];
    const float* dq    = (const float*)d_in[1];
    const float* us    = (const float*)d_in[2];
    const float* iq    = (const float*)d_in[3];
    const float* tr    = (const float*)d_in[4];
    const float* vt    = (const float*)d_in[5];
    const float* sd    = (const float*)d_in[6];
    const float* Jr    = (const float*)d_in[7];
    const float* pd    = (const float*)d_in[8];
    const float* wg    = (const float*)d_in[9];
    float* out = (float*)d_out;

    cudaFuncSetAttribute(k_mma, cudaFuncAttributeMaxDynamicSharedMemorySize, MM_SMEM);
    cudaFuncSetAttribute(k_epi, cudaFuncAttributeMaxDynamicSharedMemorySize, SMEM_EPI);

    k_A<<<25 + PP_BLKS + (BATCH * 16) / 256, 256>>>(us, sd, vt, Jr, wg, pd, theta);
    k_B<<<NM + 63 + 143 * KSPLIT, 256>>>(Jr);
    k_red2<<<(136 * 1024) / 256, 256>>>();
    k_mma<<<512, 256, MM_SMEM>>>();
    k_epi<<<NTILE, 256, SMEM_EPI>>>(theta, dq, iq, tr, out);
}